// round 3
// baseline (speedup 1.0000x reference)
#include <cuda_runtime.h>
#include <cuda_bf16.h>
#include <cstdint>
#include <cstdio>

#define T_TOK   4096
#define HID     1024
#define INTER   512
#define NE      64
#define NEZ     80
#define CAPACITY 320
#define SCALE_F 1.5f

// ---------------- scratch (static device globals; no allocation) ----------------
__device__ float g_logits[(size_t)T_TOK * NEZ];
__device__ int   g_counts[NE];
__device__ int   g_rows[NE * CAPACITY];
__device__ int   g_tok_e[T_TOK * 2];
__device__ int   g_tok_p[T_TOK * 2];
__device__ float g_tok_w[T_TOK * 2];
__device__ float g_zeroc[T_TOK];
__device__ float g_gbuf[(size_t)NE * CAPACITY * INTER];   // 42 MB
__device__ float g_ybuf[(size_t)NE * CAPACITY * HID];     // 84 MB

// ---------------- helpers ----------------
__device__ __forceinline__ float to_tf32(float x) {
    float r;
    asm("cvt.rna.tf32.f32 %0, %1;" : "=f"(r) : "f"(x));
    return r;
}

__device__ __forceinline__ void mma_tf32(float* c, const unsigned* a, const unsigned* b) {
    asm volatile(
        "mma.sync.aligned.m16n8k8.row.col.f32.tf32.tf32.f32 "
        "{%0,%1,%2,%3},{%4,%5,%6,%7},{%8,%9},{%0,%1,%2,%3};\n"
        : "+f"(c[0]), "+f"(c[1]), "+f"(c[2]), "+f"(c[3])
        : "r"(a[0]), "r"(a[1]), "r"(a[2]), "r"(a[3]), "r"(b[0]), "r"(b[1]));
}

// ---------------- kernel 0: zero expert counters ----------------
__global__ void zero_counts_kernel() {
    if (threadIdx.x < NE) g_counts[threadIdx.x] = 0;
}

// ---------------- kernel 1: router GEMM (fp32 FFMA, exact selection path) ----------
// logits[t][e] = sum_k h[t][k] * rw[e][k].  BM=64 tokens, BN=80 (all experts), BK=32.
__global__ void __launch_bounds__(256) router_gemm_kernel(
    const float* __restrict__ hs, const float* __restrict__ rw) {
    __shared__ float As[32][65];
    __shared__ float Ws[32][81];
    const int m0 = blockIdx.x * 64;
    const int tid = threadIdx.x;
    const int tm = tid & 15;     // 0..15 -> token rows tm + 16*i
    const int tn = tid >> 4;     // 0..15 -> expert cols tn + 16*j (j<5)

    float acc[4][5];
#pragma unroll
    for (int i = 0; i < 4; i++)
#pragma unroll
        for (int j = 0; j < 5; j++) acc[i][j] = 0.f;

    for (int k0 = 0; k0 < HID; k0 += 32) {
#pragma unroll
        for (int i = 0; i < 8; i++) {                // 64x32 A tile
            int lin = tid + i * 256;
            int k = lin & 31, m = lin >> 5;
            As[k][m] = hs[(size_t)(m0 + m) * HID + k0 + k];
        }
#pragma unroll
        for (int i = 0; i < 10; i++) {               // 80x32 W tile
            int lin = tid + i * 256;
            int k = lin & 31, n = lin >> 5;
            Ws[k][n] = rw[(size_t)n * HID + k0 + k];
        }
        __syncthreads();
#pragma unroll
        for (int kk = 0; kk < 32; kk++) {
            float a[4], w[5];
#pragma unroll
            for (int i = 0; i < 4; i++) a[i] = As[kk][tm + 16 * i];
#pragma unroll
            for (int j = 0; j < 5; j++) w[j] = Ws[kk][tn + 16 * j];
#pragma unroll
            for (int i = 0; i < 4; i++)
#pragma unroll
                for (int j = 0; j < 5; j++) acc[i][j] = fmaf(a[i], w[j], acc[i][j]);
        }
        __syncthreads();
    }
#pragma unroll
    for (int i = 0; i < 4; i++)
#pragma unroll
        for (int j = 0; j < 5; j++)
            g_logits[(size_t)(m0 + tm + 16 * i) * NEZ + tn + 16 * j] = acc[i][j];
}

// ---------------- kernel 2: sigmoid + top-2 + capacity dispatch ----------------
__global__ void topk_dispatch_kernel(const float* __restrict__ bias) {
    int t = blockIdx.x * blockDim.x + threadIdx.x;
    if (t >= T_TOK) return;

    float sc[NEZ];
    for (int e = 0; e < NEZ; e++) {
        float l = g_logits[(size_t)t * NEZ + e];
        sc[e] = 1.f / (1.f + expf(-l));          // accurate exp: selection robustness
    }
    // top-2 on biased scores; strict > preserves lower-index-first tie order (jax.lax.top_k)
    int i1 = -1, i2 = -1;
    float b1 = -1e30f, b2 = -1e30f;
    for (int e = 0; e < NEZ; e++) {
        float b = sc[e] + bias[e];
        if (b > b1) { b2 = b1; i2 = i1; b1 = b; i1 = e; }
        else if (b > b2) { b2 = b; i2 = e; }
    }

    float zc = 0.f;
    int sel[2] = {i1, i2};
#pragma unroll
    for (int k = 0; k < 2; k++) {
        int e = sel[k];
        float w = sc[e];                          // unbiased score, no renorm
        if (e >= NE) {                            // zero (identity) expert
            zc += w;
            g_tok_p[t * 2 + k] = -1;
            g_tok_e[t * 2 + k] = 0;
            g_tok_w[t * 2 + k] = 0.f;
        } else {
            int p = atomicAdd(&g_counts[e], 1);
            if (p < CAPACITY) g_rows[e * CAPACITY + p] = t;
            g_tok_p[t * 2 + k] = p;               // p >= CAPACITY => dropped at combine
            g_tok_e[t * 2 + k] = e;
            g_tok_w[t * 2 + k] = w;
        }
    }
    g_zeroc[t] = zc;
}

// ---------------- kernel 3: fused gate/up TF32 GEMM + SiLU  ->  g_buf -----------
// Per expert e: A = gathered hidden rows [Me,1024], B = w_gate[e], w_up[e] [1024,512]
// Block tile: 64(M) x 64(N) x 32(K). 128 threads = 2x2 warps of 32x32.
__global__ void __launch_bounds__(128) gemm_gateup_kernel(
    const float* __restrict__ hs,
    const float* __restrict__ wg,
    const float* __restrict__ wu) {
    const int e = blockIdx.z;
    const int Me = min(g_counts[e], CAPACITY);
    const int m0 = blockIdx.y * 64;
    if (m0 >= Me) return;
    const int n0 = blockIdx.x * 64;

    __shared__ float As[64][36];     // [m][k], banks 4m+k -> conflict free
    __shared__ float Bg[32][72];     // [k][n], banks 8k+n -> conflict free
    __shared__ float Bu[32][72];
    __shared__ int toks[64];

    const int tid = threadIdx.x;
    if (tid < 64) {
        int r = m0 + tid;
        toks[tid] = (r < Me) ? g_rows[e * CAPACITY + r] : -1;
    }
    __syncthreads();

    const float* wgp = wg + (size_t)e * HID * INTER + n0;
    const float* wup = wu + (size_t)e * HID * INTER + n0;

    float accG[2][4][4], accU[2][4][4];
#pragma unroll
    for (int a = 0; a < 2; a++)
#pragma unroll
        for (int b = 0; b < 4; b++)
#pragma unroll
            for (int c = 0; c < 4; c++) { accG[a][b][c] = 0.f; accU[a][b][c] = 0.f; }

    const int lane = tid & 31, warp = tid >> 5;
    const int grp = lane >> 2, tg = lane & 3;
    const int wm = (warp >> 1) * 32, wn = (warp & 1) * 32;

    for (int k0 = 0; k0 < HID; k0 += 32) {
#pragma unroll
        for (int i = 0; i < 4; i++) {             // A: 64 rows x 32 k (gathered)
            int s = tid + i * 128;
            int row = s >> 3;
            int c4 = (s & 7) * 4;
            int tok = toks[row];
            float4 v = make_float4(0.f, 0.f, 0.f, 0.f);
            if (tok >= 0) v = *(const float4*)(hs + (size_t)tok * HID + k0 + c4);
            As[row][c4 + 0] = to_tf32(v.x);
            As[row][c4 + 1] = to_tf32(v.y);
            As[row][c4 + 2] = to_tf32(v.z);
            As[row][c4 + 3] = to_tf32(v.w);
        }
#pragma unroll
        for (int i = 0; i < 4; i++) {             // B: 32 k x 64 n, gate & up
            int s = tid + i * 128;
            int k = s >> 4;
            int c4 = (s & 15) * 4;
            float4 vg = *(const float4*)(wgp + (size_t)(k0 + k) * INTER + c4);
            float4 vu = *(const float4*)(wup + (size_t)(k0 + k) * INTER + c4);
            Bg[k][c4 + 0] = to_tf32(vg.x); Bg[k][c4 + 1] = to_tf32(vg.y);
            Bg[k][c4 + 2] = to_tf32(vg.z); Bg[k][c4 + 3] = to_tf32(vg.w);
            Bu[k][c4 + 0] = to_tf32(vu.x); Bu[k][c4 + 1] = to_tf32(vu.y);
            Bu[k][c4 + 2] = to_tf32(vu.z); Bu[k][c4 + 3] = to_tf32(vu.w);
        }
        __syncthreads();
#pragma unroll
        for (int ks = 0; ks < 4; ks++) {
            const int kk = ks * 8;
            unsigned af[2][4];
#pragma unroll
            for (int mi = 0; mi < 2; mi++) {
                int mr = wm + mi * 16;
                af[mi][0] = __float_as_uint(As[mr + grp    ][kk + tg    ]);
                af[mi][1] = __float_as_uint(As[mr + grp + 8][kk + tg    ]);
                af[mi][2] = __float_as_uint(As[mr + grp    ][kk + tg + 4]);
                af[mi][3] = __float_as_uint(As[mr + grp + 8][kk + tg + 4]);
            }
#pragma unroll
            for (int ni = 0; ni < 4; ni++) {
                int nc = wn + ni * 8 + grp;
                unsigned bg2[2] = { __float_as_uint(Bg[kk + tg][nc]),
                                    __float_as_uint(Bg[kk + tg + 4][nc]) };
                unsigned bu2[2] = { __float_as_uint(Bu[kk + tg][nc]),
                                    __float_as_uint(Bu[kk + tg + 4][nc]) };
#pragma unroll
                for (int mi = 0; mi < 2; mi++) {
                    mma_tf32(accG[mi][ni], af[mi], bg2);
                    mma_tf32(accU[mi][ni], af[mi], bu2);
                }
            }
        }
        __syncthreads();
    }

    // epilogue: g = silu(gate) * up
    float* gout = g_gbuf + (size_t)e * CAPACITY * INTER;
#pragma unroll
    for (int mi = 0; mi < 2; mi++) {
#pragma unroll
        for (int half = 0; half < 2; half++) {
            int mrow = m0 + wm + mi * 16 + grp + half * 8;
            if (mrow < Me) {
#pragma unroll
                for (int ni = 0; ni < 4; ni++) {
                    int n = n0 + wn + ni * 8 + tg * 2;
                    float gv0 = accG[mi][ni][half * 2 + 0];
                    float gv1 = accG[mi][ni][half * 2 + 1];
                    float uv0 = accU[mi][ni][half * 2 + 0];
                    float uv1 = accU[mi][ni][half * 2 + 1];
                    float o0 = (gv0 / (1.f + __expf(-gv0))) * uv0;
                    float o1 = (gv1 / (1.f + __expf(-gv1))) * uv1;
                    *(float2*)(gout + (size_t)mrow * INTER + n) = make_float2(o0, o1);
                }
            }
        }
    }
}

// ---------------- kernel 4: down-proj TF32 GEMM  ->  y_buf ----------------
// Per expert e: A = g_buf[e] [Me,512], B = w_down[e] [512,1024]
__global__ void __launch_bounds__(128) gemm_down_kernel(const float* __restrict__ wd) {
    const int e = blockIdx.z;
    const int Me = min(g_counts[e], CAPACITY);
    const int m0 = blockIdx.y * 64;
    if (m0 >= Me) return;
    const int n0 = blockIdx.x * 64;

    __shared__ float As[64][36];
    __shared__ float Bs[32][72];

    const int tid = threadIdx.x;
    const float* ap = g_gbuf + (size_t)e * CAPACITY * INTER + (size_t)m0 * INTER;
    const float* bp = wd + (size_t)e * INTER * HID + n0;

    float acc[2][4][4];
#pragma unroll
    for (int a = 0; a < 2; a++)
#pragma unroll
        for (int b = 0; b < 4; b++)
#pragma unroll
            for (int c = 0; c < 4; c++) acc[a][b][c] = 0.f;

    const int lane = tid & 31, warp = tid >> 5;
    const int grp = lane >> 2, tg = lane & 3;
    const int wm = (warp >> 1) * 32, wn = (warp & 1) * 32;

    for (int k0 = 0; k0 < INTER; k0 += 32) {
#pragma unroll
        for (int i = 0; i < 4; i++) {
            int s = tid + i * 128;
            int row = s >> 3;
            int c4 = (s & 7) * 4;
            float4 v = *(const float4*)(ap + (size_t)row * INTER + k0 + c4);
            As[row][c4 + 0] = to_tf32(v.x);
            As[row][c4 + 1] = to_tf32(v.y);
            As[row][c4 + 2] = to_tf32(v.z);
            As[row][c4 + 3] = to_tf32(v.w);
        }
#pragma unroll
        for (int i = 0; i < 4; i++) {
            int s = tid + i * 128;
            int k = s >> 4;
            int c4 = (s & 15) * 4;
            float4 v = *(const float4*)(bp + (size_t)(k0 + k) * HID + c4);
            Bs[k][c4 + 0] = to_tf32(v.x); Bs[k][c4 + 1] = to_tf32(v.y);
            Bs[k][c4 + 2] = to_tf32(v.z); Bs[k][c4 + 3] = to_tf32(v.w);
        }
        __syncthreads();
#pragma unroll
        for (int ks = 0; ks < 4; ks++) {
            const int kk = ks * 8;
            unsigned af[2][4];
#pragma unroll
            for (int mi = 0; mi < 2; mi++) {
                int mr = wm + mi * 16;
                af[mi][0] = __float_as_uint(As[mr + grp    ][kk + tg    ]);
                af[mi][1] = __float_as_uint(As[mr + grp + 8][kk + tg    ]);
                af[mi][2] = __float_as_uint(As[mr + grp    ][kk + tg + 4]);
                af[mi][3] = __float_as_uint(As[mr + grp + 8][kk + tg + 4]);
            }
#pragma unroll
            for (int ni = 0; ni < 4; ni++) {
                int nc = wn + ni * 8 + grp;
                unsigned b2[2] = { __float_as_uint(Bs[kk + tg][nc]),
                                   __float_as_uint(Bs[kk + tg + 4][nc]) };
#pragma unroll
                for (int mi = 0; mi < 2; mi++) mma_tf32(acc[mi][ni], af[mi], b2);
            }
        }
        __syncthreads();
    }

    float* yout = g_ybuf + (size_t)e * CAPACITY * HID;
#pragma unroll
    for (int mi = 0; mi < 2; mi++) {
#pragma unroll
        for (int half = 0; half < 2; half++) {
            int mrow = m0 + wm + mi * 16 + grp + half * 8;
            if (mrow < Me) {
#pragma unroll
                for (int ni = 0; ni < 4; ni++) {
                    int n = n0 + wn + ni * 8 + tg * 2;
                    *(float2*)(yout + (size_t)mrow * HID + n) =
                        make_float2(acc[mi][ni][half * 2 + 0], acc[mi][ni][half * 2 + 1]);
                }
            }
        }
    }
}

// ---------------- kernel 5: deterministic combine ----------------
// out[t] = SCALE * (zero_coeff[t]*h[t] + sum_k w_k * y_buf[e_k][p_k])
__global__ void combine_kernel(const float* __restrict__ hs, float* __restrict__ out) {
    const int t = blockIdx.x;
    const int j = threadIdx.x;     // 256 threads, one float4 each
    float4 hv = *(const float4*)(hs + (size_t)t * HID + j * 4);
    float zc = g_zeroc[t];
    float4 r;
    r.x = zc * hv.x; r.y = zc * hv.y; r.z = zc * hv.z; r.w = zc * hv.w;
#pragma unroll
    for (int k = 0; k < 2; k++) {
        int p = g_tok_p[t * 2 + k];
        if (p >= 0 && p < CAPACITY) {
            int e = g_tok_e[t * 2 + k];
            float w = g_tok_w[t * 2 + k];
            float4 y = *(const float4*)(g_ybuf + ((size_t)e * CAPACITY + p) * HID + j * 4);
            r.x = fmaf(w, y.x, r.x);
            r.y = fmaf(w, y.y, r.y);
            r.z = fmaf(w, y.z, r.z);
            r.w = fmaf(w, y.w, r.w);
        }
    }
    r.x *= SCALE_F; r.y *= SCALE_F; r.z *= SCALE_F; r.w *= SCALE_F;
    *(float4*)(out + (size_t)t * HID + j * 4) = r;
}

// ---------------- launcher ----------------
extern "C" void kernel_launch(void* const* d_in, const int* in_sizes, int n_in,
                              void* d_out, int out_size) {
    const float* hs   = (const float*)d_in[0];   // [4096,1024]
    const float* rw   = (const float*)d_in[1];   // [80,1024]
    const float* bias = (const float*)d_in[2];   // [80]
    const float* wg   = (const float*)d_in[3];   // [64,1024,512]
    const float* wu   = (const float*)d_in[4];   // [64,1024,512]
    const float* wd   = (const float*)d_in[5];   // [64,512,1024]
    float* out = (float*)d_out;                  // [4096,1024]

    zero_counts_kernel<<<1, 64>>>();
    router_gemm_kernel<<<T_TOK / 64, 256>>>(hs, rw);
    topk_dispatch_kernel<<<T_TOK / 128, 128>>>(bias);
    gemm_gateup_kernel<<<dim3(INTER / 64, CAPACITY / 64, NE), 128>>>(hs, wg, wu);
    gemm_down_kernel<<<dim3(HID / 64, CAPACITY / 64, NE), 128>>>(wd);
    combine_kernel<<<T_TOK, 256>>>(hs, out);
}

// round 5
// speedup vs baseline: 1.1485x; 1.1485x over previous
#include <cuda_runtime.h>
#include <cuda_bf16.h>
#include <cstdint>
#include <cstdio>

#define T_TOK   4096
#define HID     1024
#define INTER   512
#define NE      64
#define NEZ     80
#define CAPACITY 320
#define SCALE_F 1.5f

// ---------------- scratch (static device globals; no allocation) ----------------
__device__ float g_logits[(size_t)T_TOK * NEZ];
__device__ int   g_counts[NE];
__device__ int   g_rows[NE * CAPACITY];
__device__ int   g_tok_e[T_TOK * 2];
__device__ int   g_tok_p[T_TOK * 2];
__device__ float g_tok_w[T_TOK * 2];
__device__ float g_zeroc[T_TOK];
__device__ float g_gbuf[(size_t)NE * CAPACITY * INTER];   // 42 MB
__device__ float g_ybuf[(size_t)NE * CAPACITY * HID];     // 84 MB

// ---------------- helpers ----------------
__device__ __forceinline__ float to_tf32(float x) {
    float r;
    asm("cvt.rna.tf32.f32 %0, %1;" : "=f"(r) : "f"(x));
    return r;
}

__device__ __forceinline__ void mma_tf32(float* c, const unsigned* a, const unsigned* b) {
    asm volatile(
        "mma.sync.aligned.m16n8k8.row.col.f32.tf32.tf32.f32 "
        "{%0,%1,%2,%3},{%4,%5,%6,%7},{%8,%9},{%0,%1,%2,%3};\n"
        : "+f"(c[0]), "+f"(c[1]), "+f"(c[2]), "+f"(c[3])
        : "r"(a[0]), "r"(a[1]), "r"(a[2]), "r"(a[3]), "r"(b[0]), "r"(b[1]));
}

// ---------------- kernel 0: zero expert counters ----------------
__global__ void zero_counts_kernel() {
    if (threadIdx.x < NE) g_counts[threadIdx.x] = 0;
}

// ---------------- kernel 1: router GEMM (fp32 FFMA, exact selection path) ----------
__global__ void __launch_bounds__(256) router_gemm_kernel(
    const float* __restrict__ hs, const float* __restrict__ rw) {
    __shared__ float As[32][65];
    __shared__ float Ws[32][81];
    const int m0 = blockIdx.x * 64;
    const int tid = threadIdx.x;
    const int tm = tid & 15;
    const int tn = tid >> 4;

    float acc[4][5];
#pragma unroll
    for (int i = 0; i < 4; i++)
#pragma unroll
        for (int j = 0; j < 5; j++) acc[i][j] = 0.f;

    for (int k0 = 0; k0 < HID; k0 += 32) {
#pragma unroll
        for (int i = 0; i < 8; i++) {
            int lin = tid + i * 256;
            int k = lin & 31, m = lin >> 5;
            As[k][m] = hs[(size_t)(m0 + m) * HID + k0 + k];
        }
#pragma unroll
        for (int i = 0; i < 10; i++) {
            int lin = tid + i * 256;
            int k = lin & 31, n = lin >> 5;
            Ws[k][n] = rw[(size_t)n * HID + k0 + k];
        }
        __syncthreads();
#pragma unroll
        for (int kk = 0; kk < 32; kk++) {
            float a[4], w[5];
#pragma unroll
            for (int i = 0; i < 4; i++) a[i] = As[kk][tm + 16 * i];
#pragma unroll
            for (int j = 0; j < 5; j++) w[j] = Ws[kk][tn + 16 * j];
#pragma unroll
            for (int i = 0; i < 4; i++)
#pragma unroll
                for (int j = 0; j < 5; j++) acc[i][j] = fmaf(a[i], w[j], acc[i][j]);
        }
        __syncthreads();
    }
#pragma unroll
    for (int i = 0; i < 4; i++)
#pragma unroll
        for (int j = 0; j < 5; j++)
            g_logits[(size_t)(m0 + tm + 16 * i) * NEZ + tn + 16 * j] = acc[i][j];
}

// ---------------- kernel 2: sigmoid + top-2 + capacity dispatch ----------------
__global__ void topk_dispatch_kernel(const float* __restrict__ bias) {
    int t = blockIdx.x * blockDim.x + threadIdx.x;
    if (t >= T_TOK) return;

    float sc[NEZ];
    for (int e = 0; e < NEZ; e++) {
        float l = g_logits[(size_t)t * NEZ + e];
        sc[e] = 1.f / (1.f + expf(-l));
    }
    int i1 = -1, i2 = -1;
    float b1 = -1e30f, b2 = -1e30f;
    for (int e = 0; e < NEZ; e++) {
        float b = sc[e] + bias[e];
        if (b > b1) { b2 = b1; i2 = i1; b1 = b; i1 = e; }
        else if (b > b2) { b2 = b; i2 = e; }
    }

    float zc = 0.f;
    int sel[2] = {i1, i2};
#pragma unroll
    for (int k = 0; k < 2; k++) {
        int e = sel[k];
        float w = sc[e];
        if (e >= NE) {
            zc += w;
            g_tok_p[t * 2 + k] = -1;
            g_tok_e[t * 2 + k] = 0;
            g_tok_w[t * 2 + k] = 0.f;
        } else {
            int p = atomicAdd(&g_counts[e], 1);
            if (p < CAPACITY) g_rows[e * CAPACITY + p] = t;
            g_tok_p[t * 2 + k] = p;
            g_tok_e[t * 2 + k] = e;
            g_tok_w[t * 2 + k] = w;
        }
    }
    g_zeroc[t] = zc;
}

// ---------------- kernel 3: fused gate/up TF32 GEMM + SiLU  ->  g_buf -----------
// Tile 128M x 64N x 16K, 256 threads (8 warps of 32x32), double-buffered smem,
// single __syncthreads per K-step, global loads for step k+1 overlap MMA of step k.
__global__ void __launch_bounds__(256, 2) gemm_gateup_kernel(
    const float* __restrict__ hs,
    const float* __restrict__ wg,
    const float* __restrict__ wu) {
    const int e = blockIdx.z;
    const int Me = min(g_counts[e], CAPACITY);
    const int m0 = blockIdx.y * 128;
    if (m0 >= Me) return;
    const int n0 = blockIdx.x * 64;

    __shared__ float As[2][128][20];    // [m][k], stride 20: LDS banks 20*grp+tg all-distinct
    __shared__ float Bgs[2][16][72];    // [k][n], stride 72: 8*tg+grp all-distinct
    __shared__ float Bus[2][16][72];
    __shared__ int toks[128];

    const int tid = threadIdx.x;
    if (tid < 128) {
        int r = m0 + tid;
        toks[tid] = (r < Me) ? g_rows[e * CAPACITY + r] : -1;
    }
    __syncthreads();

    const float* wgp = wg + (size_t)e * HID * INTER + n0;
    const float* wup = wu + (size_t)e * HID * INTER + n0;

    const int arow = tid >> 2;          // 0..63 (second slice +64)
    const int ac4  = (tid & 3) * 4;     // k offset within BK=16
    const int brow = tid >> 4;          // 0..15 (k)
    const int bc4  = (tid & 15) * 4;    // n offset

    const int tokA0 = toks[arow];
    const int tokA1 = toks[arow + 64];
    const float* aP0 = (tokA0 >= 0) ? hs + (size_t)tokA0 * HID + ac4 : (const float*)0;
    const float* aP1 = (tokA1 >= 0) ? hs + (size_t)tokA1 * HID + ac4 : (const float*)0;

    float4 aR0, aR1, gR, uR;

    auto fetch = [&](int k0) {
        aR0 = aP0 ? *(const float4*)(aP0 + k0) : make_float4(0.f, 0.f, 0.f, 0.f);
        aR1 = aP1 ? *(const float4*)(aP1 + k0) : make_float4(0.f, 0.f, 0.f, 0.f);
        gR = *(const float4*)(wgp + (size_t)(k0 + brow) * INTER + bc4);
        uR = *(const float4*)(wup + (size_t)(k0 + brow) * INTER + bc4);
    };
    auto stage = [&](int buf) {
        As[buf][arow][ac4 + 0] = to_tf32(aR0.x);
        As[buf][arow][ac4 + 1] = to_tf32(aR0.y);
        As[buf][arow][ac4 + 2] = to_tf32(aR0.z);
        As[buf][arow][ac4 + 3] = to_tf32(aR0.w);
        As[buf][arow + 64][ac4 + 0] = to_tf32(aR1.x);
        As[buf][arow + 64][ac4 + 1] = to_tf32(aR1.y);
        As[buf][arow + 64][ac4 + 2] = to_tf32(aR1.z);
        As[buf][arow + 64][ac4 + 3] = to_tf32(aR1.w);
        Bgs[buf][brow][bc4 + 0] = to_tf32(gR.x);
        Bgs[buf][brow][bc4 + 1] = to_tf32(gR.y);
        Bgs[buf][brow][bc4 + 2] = to_tf32(gR.z);
        Bgs[buf][brow][bc4 + 3] = to_tf32(gR.w);
        Bus[buf][brow][bc4 + 0] = to_tf32(uR.x);
        Bus[buf][brow][bc4 + 1] = to_tf32(uR.y);
        Bus[buf][brow][bc4 + 2] = to_tf32(uR.z);
        Bus[buf][brow][bc4 + 3] = to_tf32(uR.w);
    };

    float accG[2][4][4], accU[2][4][4];
#pragma unroll
    for (int a = 0; a < 2; a++)
#pragma unroll
        for (int b = 0; b < 4; b++)
#pragma unroll
            for (int c = 0; c < 4; c++) { accG[a][b][c] = 0.f; accU[a][b][c] = 0.f; }

    const int lane = tid & 31, warp = tid >> 5;
    const int grp = lane >> 2, tg = lane & 3;
    const int wm = (warp >> 1) * 32, wn = (warp & 1) * 32;

    fetch(0);
    stage(0);
    __syncthreads();

    const int KT = HID / 16;   // 64
    for (int kt = 0; kt < KT; kt++) {
        const int p = kt & 1;
        if (kt + 1 < KT) fetch((kt + 1) * 16);
#pragma unroll
        for (int ks = 0; ks < 16; ks += 8) {
            unsigned af[2][4];
#pragma unroll
            for (int mi = 0; mi < 2; mi++) {
                int mr = wm + mi * 16;
                af[mi][0] = __float_as_uint(As[p][mr + grp    ][ks + tg    ]);
                af[mi][1] = __float_as_uint(As[p][mr + grp + 8][ks + tg    ]);
                af[mi][2] = __float_as_uint(As[p][mr + grp    ][ks + tg + 4]);
                af[mi][3] = __float_as_uint(As[p][mr + grp + 8][ks + tg + 4]);
            }
#pragma unroll
            for (int ni = 0; ni < 4; ni++) {
                int nc = wn + ni * 8 + grp;
                unsigned bg2[2] = { __float_as_uint(Bgs[p][ks + tg][nc]),
                                    __float_as_uint(Bgs[p][ks + tg + 4][nc]) };
                unsigned bu2[2] = { __float_as_uint(Bus[p][ks + tg][nc]),
                                    __float_as_uint(Bus[p][ks + tg + 4][nc]) };
#pragma unroll
                for (int mi = 0; mi < 2; mi++) {
                    mma_tf32(accG[mi][ni], af[mi], bg2);
                    mma_tf32(accU[mi][ni], af[mi], bu2);
                }
            }
        }
        if (kt + 1 < KT) stage(p ^ 1);
        __syncthreads();
    }

    // epilogue: g = silu(gate) * up
    float* gout = g_gbuf + (size_t)e * CAPACITY * INTER;
#pragma unroll
    for (int mi = 0; mi < 2; mi++) {
#pragma unroll
        for (int half = 0; half < 2; half++) {
            int mrow = m0 + wm + mi * 16 + grp + half * 8;
            if (mrow < Me) {
#pragma unroll
                for (int ni = 0; ni < 4; ni++) {
                    int n = n0 + wn + ni * 8 + tg * 2;
                    float gv0 = accG[mi][ni][half * 2 + 0];
                    float gv1 = accG[mi][ni][half * 2 + 1];
                    float uv0 = accU[mi][ni][half * 2 + 0];
                    float uv1 = accU[mi][ni][half * 2 + 1];
                    float o0 = (gv0 / (1.f + __expf(-gv0))) * uv0;
                    float o1 = (gv1 / (1.f + __expf(-gv1))) * uv1;
                    *(float2*)(gout + (size_t)mrow * INTER + n) = make_float2(o0, o1);
                }
            }
        }
    }
}

// ---------------- kernel 4: down-proj TF32 GEMM  ->  y_buf ----------------
// Tile 128M x 64N x 16K, double-buffered, same schedule as gateup.
__global__ void __launch_bounds__(256, 2) gemm_down_kernel(const float* __restrict__ wd) {
    const int e = blockIdx.z;
    const int Me = min(g_counts[e], CAPACITY);
    const int m0 = blockIdx.y * 128;
    if (m0 >= Me) return;
    const int n0 = blockIdx.x * 64;

    __shared__ float As[2][128][20];
    __shared__ float Bs[2][16][72];

    const int tid = threadIdx.x;
    const float* bp = wd + (size_t)e * INTER * HID + n0;

    const int arow = tid >> 2;
    const int ac4  = (tid & 3) * 4;
    const int brow = tid >> 4;
    const int bc4  = (tid & 15) * 4;

    // rows beyond CAPACITY (tile padding on last M-tile) must not read OOB
    const bool v0 = (m0 + arow) < CAPACITY;
    const bool v1 = (m0 + arow + 64) < CAPACITY;
    const float* aP0 = g_gbuf + ((size_t)e * CAPACITY + m0 + arow) * INTER + ac4;
    const float* aP1 = g_gbuf + ((size_t)e * CAPACITY + m0 + arow + 64) * INTER + ac4;

    float4 aR0, aR1, bR;
    auto fetch = [&](int k0) {
        aR0 = v0 ? *(const float4*)(aP0 + k0) : make_float4(0.f, 0.f, 0.f, 0.f);
        aR1 = v1 ? *(const float4*)(aP1 + k0) : make_float4(0.f, 0.f, 0.f, 0.f);
        bR = *(const float4*)(bp + (size_t)(k0 + brow) * HID + bc4);
    };
    auto stage = [&](int buf) {
        As[buf][arow][ac4 + 0] = to_tf32(aR0.x);
        As[buf][arow][ac4 + 1] = to_tf32(aR0.y);
        As[buf][arow][ac4 + 2] = to_tf32(aR0.z);
        As[buf][arow][ac4 + 3] = to_tf32(aR0.w);
        As[buf][arow + 64][ac4 + 0] = to_tf32(aR1.x);
        As[buf][arow + 64][ac4 + 1] = to_tf32(aR1.y);
        As[buf][arow + 64][ac4 + 2] = to_tf32(aR1.z);
        As[buf][arow + 64][ac4 + 3] = to_tf32(aR1.w);
        Bs[buf][brow][bc4 + 0] = to_tf32(bR.x);
        Bs[buf][brow][bc4 + 1] = to_tf32(bR.y);
        Bs[buf][brow][bc4 + 2] = to_tf32(bR.z);
        Bs[buf][brow][bc4 + 3] = to_tf32(bR.w);
    };

    float acc[2][4][4];
#pragma unroll
    for (int a = 0; a < 2; a++)
#pragma unroll
        for (int b = 0; b < 4; b++)
#pragma unroll
            for (int c = 0; c < 4; c++) acc[a][b][c] = 0.f;

    const int lane = tid & 31, warp = tid >> 5;
    const int grp = lane >> 2, tg = lane & 3;
    const int wm = (warp >> 1) * 32, wn = (warp & 1) * 32;

    fetch(0);
    stage(0);
    __syncthreads();

    const int KT = INTER / 16;   // 32
    for (int kt = 0; kt < KT; kt++) {
        const int p = kt & 1;
        if (kt + 1 < KT) fetch((kt + 1) * 16);
#pragma unroll
        for (int ks = 0; ks < 16; ks += 8) {
            unsigned af[2][4];
#pragma unroll
            for (int mi = 0; mi < 2; mi++) {
                int mr = wm + mi * 16;
                af[mi][0] = __float_as_uint(As[p][mr + grp    ][ks + tg    ]);
                af[mi][1] = __float_as_uint(As[p][mr + grp + 8][ks + tg    ]);
                af[mi][2] = __float_as_uint(As[p][mr + grp    ][ks + tg + 4]);
                af[mi][3] = __float_as_uint(As[p][mr + grp + 8][ks + tg + 4]);
            }
#pragma unroll
            for (int ni = 0; ni < 4; ni++) {
                int nc = wn + ni * 8 + grp;
                unsigned b2[2] = { __float_as_uint(Bs[p][ks + tg][nc]),
                                   __float_as_uint(Bs[p][ks + tg + 4][nc]) };
#pragma unroll
                for (int mi = 0; mi < 2; mi++) mma_tf32(acc[mi][ni], af[mi], b2);
            }
        }
        if (kt + 1 < KT) stage(p ^ 1);
        __syncthreads();
    }

    float* yout = g_ybuf + (size_t)e * CAPACITY * HID;
#pragma unroll
    for (int mi = 0; mi < 2; mi++) {
#pragma unroll
        for (int half = 0; half < 2; half++) {
            int mrow = m0 + wm + mi * 16 + grp + half * 8;
            if (mrow < Me) {
#pragma unroll
                for (int ni = 0; ni < 4; ni++) {
                    int n = n0 + wn + ni * 8 + tg * 2;
                    *(float2*)(yout + (size_t)mrow * HID + n) =
                        make_float2(acc[mi][ni][half * 2 + 0], acc[mi][ni][half * 2 + 1]);
                }
            }
        }
    }
}

// ---------------- kernel 5: deterministic combine ----------------
__global__ void combine_kernel(const float* __restrict__ hs, float* __restrict__ out) {
    const int t = blockIdx.x;
    const int j = threadIdx.x;
    float4 hv = *(const float4*)(hs + (size_t)t * HID + j * 4);
    float zc = g_zeroc[t];
    float4 r;
    r.x = zc * hv.x; r.y = zc * hv.y; r.z = zc * hv.z; r.w = zc * hv.w;
#pragma unroll
    for (int k = 0; k < 2; k++) {
        int p = g_tok_p[t * 2 + k];
        if (p >= 0 && p < CAPACITY) {
            int e = g_tok_e[t * 2 + k];
            float w = g_tok_w[t * 2 + k];
            float4 y = *(const float4*)(g_ybuf + ((size_t)e * CAPACITY + p) * HID + j * 4);
            r.x = fmaf(w, y.x, r.x);
            r.y = fmaf(w, y.y, r.y);
            r.z = fmaf(w, y.z, r.z);
            r.w = fmaf(w, y.w, r.w);
        }
    }
    r.x *= SCALE_F; r.y *= SCALE_F; r.z *= SCALE_F; r.w *= SCALE_F;
    *(float4*)(out + (size_t)t * HID + j * 4) = r;
}

// ---------------- launcher ----------------
extern "C" void kernel_launch(void* const* d_in, const int* in_sizes, int n_in,
                              void* d_out, int out_size) {
    const float* hs   = (const float*)d_in[0];   // [4096,1024]
    const float* rw   = (const float*)d_in[1];   // [80,1024]
    const float* bias = (const float*)d_in[2];   // [80]
    const float* wg   = (const float*)d_in[3];   // [64,1024,512]
    const float* wu   = (const float*)d_in[4];   // [64,1024,512]
    const float* wd   = (const float*)d_in[5];   // [64,512,1024]
    float* out = (float*)d_out;                  // [4096,1024]

    zero_counts_kernel<<<1, 64>>>();
    router_gemm_kernel<<<T_TOK / 64, 256>>>(hs, rw);
    topk_dispatch_kernel<<<T_TOK / 128, 128>>>(bias);
    gemm_gateup_kernel<<<dim3(INTER / 64, (CAPACITY + 127) / 128, NE), 256>>>(hs, wg, wu);
    gemm_down_kernel<<<dim3(HID / 64, (CAPACITY + 127) / 128, NE), 256>>>(wd);
    combine_kernel<<<T_TOK, 256>>>(hs, out);
}

// round 6
// speedup vs baseline: 1.1489x; 1.0003x over previous
#include <cuda_runtime.h>
#include <cuda_bf16.h>
#include <cstdint>
#include <cstdio>

#define T_TOK   4096
#define HID     1024
#define INTER   512
#define NE      64
#define NEZ     80
#define CAPACITY 320
#define SCALE_F 1.5f

// ---------------- scratch (static device globals; no allocation) ----------------
__device__ float g_logits[(size_t)T_TOK * NEZ];
__device__ int   g_counts[NE];
__device__ int   g_rows[NE * CAPACITY];
__device__ int   g_tok_e[T_TOK * 2];
__device__ int   g_tok_p[T_TOK * 2];
__device__ float g_tok_w[T_TOK * 2];
__device__ float g_zeroc[T_TOK];
__device__ float g_gbuf[(size_t)NE * CAPACITY * INTER];   // 42 MB
__device__ float g_ybuf[(size_t)NE * CAPACITY * HID];     // 84 MB

// ---------------- helpers ----------------
__device__ __forceinline__ float to_tf32(float x) {
    float r;
    asm("cvt.rna.tf32.f32 %0, %1;" : "=f"(r) : "f"(x));
    return r;
}

__device__ __forceinline__ void mma_tf32(float* c, const unsigned* a, const unsigned* b) {
    asm volatile(
        "mma.sync.aligned.m16n8k8.row.col.f32.tf32.tf32.f32 "
        "{%0,%1,%2,%3},{%4,%5,%6,%7},{%8,%9},{%0,%1,%2,%3};\n"
        : "+f"(c[0]), "+f"(c[1]), "+f"(c[2]), "+f"(c[3])
        : "r"(a[0]), "r"(a[1]), "r"(a[2]), "r"(a[3]), "r"(b[0]), "r"(b[1]));
}

// ---------------- kernel 0: zero expert counters ----------------
__global__ void zero_counts_kernel() {
    if (threadIdx.x < NE) g_counts[threadIdx.x] = 0;
}

// ---------------- kernel 1: router GEMM (fp32 FFMA, exact selection path) ----------
__global__ void __launch_bounds__(256) router_gemm_kernel(
    const float* __restrict__ hs, const float* __restrict__ rw) {
    __shared__ float As[32][65];
    __shared__ float Ws[32][81];
    const int m0 = blockIdx.x * 64;
    const int tid = threadIdx.x;
    const int tm = tid & 15;
    const int tn = tid >> 4;

    float acc[4][5];
#pragma unroll
    for (int i = 0; i < 4; i++)
#pragma unroll
        for (int j = 0; j < 5; j++) acc[i][j] = 0.f;

    for (int k0 = 0; k0 < HID; k0 += 32) {
#pragma unroll
        for (int i = 0; i < 8; i++) {
            int lin = tid + i * 256;
            int k = lin & 31, m = lin >> 5;
            As[k][m] = hs[(size_t)(m0 + m) * HID + k0 + k];
        }
#pragma unroll
        for (int i = 0; i < 10; i++) {
            int lin = tid + i * 256;
            int k = lin & 31, n = lin >> 5;
            Ws[k][n] = rw[(size_t)n * HID + k0 + k];
        }
        __syncthreads();
#pragma unroll
        for (int kk = 0; kk < 32; kk++) {
            float a[4], w[5];
#pragma unroll
            for (int i = 0; i < 4; i++) a[i] = As[kk][tm + 16 * i];
#pragma unroll
            for (int j = 0; j < 5; j++) w[j] = Ws[kk][tn + 16 * j];
#pragma unroll
            for (int i = 0; i < 4; i++)
#pragma unroll
                for (int j = 0; j < 5; j++) acc[i][j] = fmaf(a[i], w[j], acc[i][j]);
        }
        __syncthreads();
    }
#pragma unroll
    for (int i = 0; i < 4; i++)
#pragma unroll
        for (int j = 0; j < 5; j++)
            g_logits[(size_t)(m0 + tm + 16 * i) * NEZ + tn + 16 * j] = acc[i][j];
}

// ---------------- kernel 2: sigmoid + top-2 + capacity dispatch ----------------
__global__ void topk_dispatch_kernel(const float* __restrict__ bias) {
    int t = blockIdx.x * blockDim.x + threadIdx.x;
    if (t >= T_TOK) return;

    float sc[NEZ];
    for (int e = 0; e < NEZ; e++) {
        float l = g_logits[(size_t)t * NEZ + e];
        sc[e] = 1.f / (1.f + expf(-l));
    }
    int i1 = -1, i2 = -1;
    float b1 = -1e30f, b2 = -1e30f;
    for (int e = 0; e < NEZ; e++) {
        float b = sc[e] + bias[e];
        if (b > b1) { b2 = b1; i2 = i1; b1 = b; i1 = e; }
        else if (b > b2) { b2 = b; i2 = e; }
    }

    float zc = 0.f;
    int sel[2] = {i1, i2};
#pragma unroll
    for (int k = 0; k < 2; k++) {
        int e = sel[k];
        float w = sc[e];
        if (e >= NE) {
            zc += w;
            g_tok_p[t * 2 + k] = -1;
            g_tok_e[t * 2 + k] = 0;
            g_tok_w[t * 2 + k] = 0.f;
        } else {
            int p = atomicAdd(&g_counts[e], 1);
            if (p < CAPACITY) g_rows[e * CAPACITY + p] = t;
            g_tok_p[t * 2 + k] = p;
            g_tok_e[t * 2 + k] = e;
            g_tok_w[t * 2 + k] = w;
        }
    }
    g_zeroc[t] = zc;
}

// ---------------- kernel 3: fused gate/up TF32 GEMM + SiLU  ->  g_buf -----------
// Tile 128M x 64N x 16K, 256 threads (8 warps of 32x32), double-buffered smem,
// single __syncthreads per K-step, global loads for step k+1 overlap MMA of step k.
__global__ void __launch_bounds__(256, 2) gemm_gateup_kernel(
    const float* __restrict__ hs,
    const float* __restrict__ wg,
    const float* __restrict__ wu) {
    const int e = blockIdx.z;
    const int Me = min(g_counts[e], CAPACITY);
    const int m0 = blockIdx.y * 128;
    if (m0 >= Me) return;
    const int n0 = blockIdx.x * 64;

    __shared__ float As[2][128][20];    // [m][k], stride 20: LDS banks 20*grp+tg all-distinct
    __shared__ float Bgs[2][16][72];    // [k][n], stride 72: 8*tg+grp all-distinct
    __shared__ float Bus[2][16][72];
    __shared__ int toks[128];

    const int tid = threadIdx.x;
    if (tid < 128) {
        int r = m0 + tid;
        toks[tid] = (r < Me) ? g_rows[e * CAPACITY + r] : -1;
    }
    __syncthreads();

    const float* wgp = wg + (size_t)e * HID * INTER + n0;
    const float* wup = wu + (size_t)e * HID * INTER + n0;

    const int arow = tid >> 2;          // 0..63 (second slice +64)
    const int ac4  = (tid & 3) * 4;     // k offset within BK=16
    const int brow = tid >> 4;          // 0..15 (k)
    const int bc4  = (tid & 15) * 4;    // n offset

    const int tokA0 = toks[arow];
    const int tokA1 = toks[arow + 64];
    const float* aP0 = (tokA0 >= 0) ? hs + (size_t)tokA0 * HID + ac4 : (const float*)0;
    const float* aP1 = (tokA1 >= 0) ? hs + (size_t)tokA1 * HID + ac4 : (const float*)0;

    float4 aR0, aR1, gR, uR;

    auto fetch = [&](int k0) {
        aR0 = aP0 ? *(const float4*)(aP0 + k0) : make_float4(0.f, 0.f, 0.f, 0.f);
        aR1 = aP1 ? *(const float4*)(aP1 + k0) : make_float4(0.f, 0.f, 0.f, 0.f);
        gR = *(const float4*)(wgp + (size_t)(k0 + brow) * INTER + bc4);
        uR = *(const float4*)(wup + (size_t)(k0 + brow) * INTER + bc4);
    };
    auto stage = [&](int buf) {
        As[buf][arow][ac4 + 0] = to_tf32(aR0.x);
        As[buf][arow][ac4 + 1] = to_tf32(aR0.y);
        As[buf][arow][ac4 + 2] = to_tf32(aR0.z);
        As[buf][arow][ac4 + 3] = to_tf32(aR0.w);
        As[buf][arow + 64][ac4 + 0] = to_tf32(aR1.x);
        As[buf][arow + 64][ac4 + 1] = to_tf32(aR1.y);
        As[buf][arow + 64][ac4 + 2] = to_tf32(aR1.z);
        As[buf][arow + 64][ac4 + 3] = to_tf32(aR1.w);
        Bgs[buf][brow][bc4 + 0] = to_tf32(gR.x);
        Bgs[buf][brow][bc4 + 1] = to_tf32(gR.y);
        Bgs[buf][brow][bc4 + 2] = to_tf32(gR.z);
        Bgs[buf][brow][bc4 + 3] = to_tf32(gR.w);
        Bus[buf][brow][bc4 + 0] = to_tf32(uR.x);
        Bus[buf][brow][bc4 + 1] = to_tf32(uR.y);
        Bus[buf][brow][bc4 + 2] = to_tf32(uR.z);
        Bus[buf][brow][bc4 + 3] = to_tf32(uR.w);
    };

    float accG[2][4][4], accU[2][4][4];
#pragma unroll
    for (int a = 0; a < 2; a++)
#pragma unroll
        for (int b = 0; b < 4; b++)
#pragma unroll
            for (int c = 0; c < 4; c++) { accG[a][b][c] = 0.f; accU[a][b][c] = 0.f; }

    const int lane = tid & 31, warp = tid >> 5;
    const int grp = lane >> 2, tg = lane & 3;
    const int wm = (warp >> 1) * 32, wn = (warp & 1) * 32;

    fetch(0);
    stage(0);
    __syncthreads();

    const int KT = HID / 16;   // 64
    for (int kt = 0; kt < KT; kt++) {
        const int p = kt & 1;
        if (kt + 1 < KT) fetch((kt + 1) * 16);
#pragma unroll
        for (int ks = 0; ks < 16; ks += 8) {
            unsigned af[2][4];
#pragma unroll
            for (int mi = 0; mi < 2; mi++) {
                int mr = wm + mi * 16;
                af[mi][0] = __float_as_uint(As[p][mr + grp    ][ks + tg    ]);
                af[mi][1] = __float_as_uint(As[p][mr + grp + 8][ks + tg    ]);
                af[mi][2] = __float_as_uint(As[p][mr + grp    ][ks + tg + 4]);
                af[mi][3] = __float_as_uint(As[p][mr + grp + 8][ks + tg + 4]);
            }
#pragma unroll
            for (int ni = 0; ni < 4; ni++) {
                int nc = wn + ni * 8 + grp;
                unsigned bg2[2] = { __float_as_uint(Bgs[p][ks + tg][nc]),
                                    __float_as_uint(Bgs[p][ks + tg + 4][nc]) };
                unsigned bu2[2] = { __float_as_uint(Bus[p][ks + tg][nc]),
                                    __float_as_uint(Bus[p][ks + tg + 4][nc]) };
#pragma unroll
                for (int mi = 0; mi < 2; mi++) {
                    mma_tf32(accG[mi][ni], af[mi], bg2);
                    mma_tf32(accU[mi][ni], af[mi], bu2);
                }
            }
        }
        if (kt + 1 < KT) stage(p ^ 1);
        __syncthreads();
    }

    // epilogue: g = silu(gate) * up
    float* gout = g_gbuf + (size_t)e * CAPACITY * INTER;
#pragma unroll
    for (int mi = 0; mi < 2; mi++) {
#pragma unroll
        for (int half = 0; half < 2; half++) {
            int mrow = m0 + wm + mi * 16 + grp + half * 8;
            if (mrow < Me) {
#pragma unroll
                for (int ni = 0; ni < 4; ni++) {
                    int n = n0 + wn + ni * 8 + tg * 2;
                    float gv0 = accG[mi][ni][half * 2 + 0];
                    float gv1 = accG[mi][ni][half * 2 + 1];
                    float uv0 = accU[mi][ni][half * 2 + 0];
                    float uv1 = accU[mi][ni][half * 2 + 1];
                    float o0 = (gv0 / (1.f + __expf(-gv0))) * uv0;
                    float o1 = (gv1 / (1.f + __expf(-gv1))) * uv1;
                    *(float2*)(gout + (size_t)mrow * INTER + n) = make_float2(o0, o1);
                }
            }
        }
    }
}

// ---------------- kernel 4: down-proj TF32 GEMM  ->  y_buf ----------------
// Tile 128M x 64N x 16K, double-buffered, same schedule as gateup.
__global__ void __launch_bounds__(256, 2) gemm_down_kernel(const float* __restrict__ wd) {
    const int e = blockIdx.z;
    const int Me = min(g_counts[e], CAPACITY);
    const int m0 = blockIdx.y * 128;
    if (m0 >= Me) return;
    const int n0 = blockIdx.x * 64;

    __shared__ float As[2][128][20];
    __shared__ float Bs[2][16][72];

    const int tid = threadIdx.x;
    const float* bp = wd + (size_t)e * INTER * HID + n0;

    const int arow = tid >> 2;
    const int ac4  = (tid & 3) * 4;
    const int brow = tid >> 4;
    const int bc4  = (tid & 15) * 4;

    // rows beyond CAPACITY (tile padding on last M-tile) must not read OOB
    const bool v0 = (m0 + arow) < CAPACITY;
    const bool v1 = (m0 + arow + 64) < CAPACITY;
    const float* aP0 = g_gbuf + ((size_t)e * CAPACITY + m0 + arow) * INTER + ac4;
    const float* aP1 = g_gbuf + ((size_t)e * CAPACITY + m0 + arow + 64) * INTER + ac4;

    float4 aR0, aR1, bR;
    auto fetch = [&](int k0) {
        aR0 = v0 ? *(const float4*)(aP0 + k0) : make_float4(0.f, 0.f, 0.f, 0.f);
        aR1 = v1 ? *(const float4*)(aP1 + k0) : make_float4(0.f, 0.f, 0.f, 0.f);
        bR = *(const float4*)(bp + (size_t)(k0 + brow) * HID + bc4);
    };
    auto stage = [&](int buf) {
        As[buf][arow][ac4 + 0] = to_tf32(aR0.x);
        As[buf][arow][ac4 + 1] = to_tf32(aR0.y);
        As[buf][arow][ac4 + 2] = to_tf32(aR0.z);
        As[buf][arow][ac4 + 3] = to_tf32(aR0.w);
        As[buf][arow + 64][ac4 + 0] = to_tf32(aR1.x);
        As[buf][arow + 64][ac4 + 1] = to_tf32(aR1.y);
        As[buf][arow + 64][ac4 + 2] = to_tf32(aR1.z);
        As[buf][arow + 64][ac4 + 3] = to_tf32(aR1.w);
        Bs[buf][brow][bc4 + 0] = to_tf32(bR.x);
        Bs[buf][brow][bc4 + 1] = to_tf32(bR.y);
        Bs[buf][brow][bc4 + 2] = to_tf32(bR.z);
        Bs[buf][brow][bc4 + 3] = to_tf32(bR.w);
    };

    float acc[2][4][4];
#pragma unroll
    for (int a = 0; a < 2; a++)
#pragma unroll
        for (int b = 0; b < 4; b++)
#pragma unroll
            for (int c = 0; c < 4; c++) acc[a][b][c] = 0.f;

    const int lane = tid & 31, warp = tid >> 5;
    const int grp = lane >> 2, tg = lane & 3;
    const int wm = (warp >> 1) * 32, wn = (warp & 1) * 32;

    fetch(0);
    stage(0);
    __syncthreads();

    const int KT = INTER / 16;   // 32
    for (int kt = 0; kt < KT; kt++) {
        const int p = kt & 1;
        if (kt + 1 < KT) fetch((kt + 1) * 16);
#pragma unroll
        for (int ks = 0; ks < 16; ks += 8) {
            unsigned af[2][4];
#pragma unroll
            for (int mi = 0; mi < 2; mi++) {
                int mr = wm + mi * 16;
                af[mi][0] = __float_as_uint(As[p][mr + grp    ][ks + tg    ]);
                af[mi][1] = __float_as_uint(As[p][mr + grp + 8][ks + tg    ]);
                af[mi][2] = __float_as_uint(As[p][mr + grp    ][ks + tg + 4]);
                af[mi][3] = __float_as_uint(As[p][mr + grp + 8][ks + tg + 4]);
            }
#pragma unroll
            for (int ni = 0; ni < 4; ni++) {
                int nc = wn + ni * 8 + grp;
                unsigned b2[2] = { __float_as_uint(Bs[p][ks + tg][nc]),
                                   __float_as_uint(Bs[p][ks + tg + 4][nc]) };
#pragma unroll
                for (int mi = 0; mi < 2; mi++) mma_tf32(acc[mi][ni], af[mi], b2);
            }
        }
        if (kt + 1 < KT) stage(p ^ 1);
        __syncthreads();
    }

    float* yout = g_ybuf + (size_t)e * CAPACITY * HID;
#pragma unroll
    for (int mi = 0; mi < 2; mi++) {
#pragma unroll
        for (int half = 0; half < 2; half++) {
            int mrow = m0 + wm + mi * 16 + grp + half * 8;
            if (mrow < Me) {
#pragma unroll
                for (int ni = 0; ni < 4; ni++) {
                    int n = n0 + wn + ni * 8 + tg * 2;
                    *(float2*)(yout + (size_t)mrow * HID + n) =
                        make_float2(acc[mi][ni][half * 2 + 0], acc[mi][ni][half * 2 + 1]);
                }
            }
        }
    }
}

// ---------------- kernel 5: deterministic combine ----------------
__global__ void combine_kernel(const float* __restrict__ hs, float* __restrict__ out) {
    const int t = blockIdx.x;
    const int j = threadIdx.x;
    float4 hv = *(const float4*)(hs + (size_t)t * HID + j * 4);
    float zc = g_zeroc[t];
    float4 r;
    r.x = zc * hv.x; r.y = zc * hv.y; r.z = zc * hv.z; r.w = zc * hv.w;
#pragma unroll
    for (int k = 0; k < 2; k++) {
        int p = g_tok_p[t * 2 + k];
        if (p >= 0 && p < CAPACITY) {
            int e = g_tok_e[t * 2 + k];
            float w = g_tok_w[t * 2 + k];
            float4 y = *(const float4*)(g_ybuf + ((size_t)e * CAPACITY + p) * HID + j * 4);
            r.x = fmaf(w, y.x, r.x);
            r.y = fmaf(w, y.y, r.y);
            r.z = fmaf(w, y.z, r.z);
            r.w = fmaf(w, y.w, r.w);
        }
    }
    r.x *= SCALE_F; r.y *= SCALE_F; r.z *= SCALE_F; r.w *= SCALE_F;
    *(float4*)(out + (size_t)t * HID + j * 4) = r;
}

// ---------------- launcher ----------------
extern "C" void kernel_launch(void* const* d_in, const int* in_sizes, int n_in,
                              void* d_out, int out_size) {
    const float* hs   = (const float*)d_in[0];   // [4096,1024]
    const float* rw   = (const float*)d_in[1];   // [80,1024]
    const float* bias = (const float*)d_in[2];   // [80]
    const float* wg   = (const float*)d_in[3];   // [64,1024,512]
    const float* wu   = (const float*)d_in[4];   // [64,1024,512]
    const float* wd   = (const float*)d_in[5];   // [64,512,1024]
    float* out = (float*)d_out;                  // [4096,1024]

    zero_counts_kernel<<<1, 64>>>();
    router_gemm_kernel<<<T_TOK / 64, 256>>>(hs, rw);
    topk_dispatch_kernel<<<T_TOK / 128, 128>>>(bias);
    gemm_gateup_kernel<<<dim3(INTER / 64, (CAPACITY + 127) / 128, NE), 256>>>(hs, wg, wu);
    gemm_down_kernel<<<dim3(HID / 64, (CAPACITY + 127) / 128, NE), 256>>>(wd);
    combine_kernel<<<T_TOK, 256>>>(hs, out);
}

// round 8
// speedup vs baseline: 1.5707x; 1.3672x over previous
#include <cuda_runtime.h>
#include <cuda_fp16.h>
#include <cstdint>

#define T_TOK   4096
#define HID     1024
#define INTER   512
#define NE      64
#define NEZ     80
#define CAPACITY 320
#define SCALE_F 1.5f

// ---------------- scratch (static device globals; no allocation) ----------------
__device__ float g_logits[(size_t)T_TOK * NEZ];
__device__ int   g_counts[NE];
__device__ int   g_rows[NE * CAPACITY];
__device__ int   g_tok_e[T_TOK * 2];
__device__ int   g_tok_p[T_TOK * 2];
__device__ float g_tok_w[T_TOK * 2];
__device__ float g_zeroc[T_TOK];
__device__ float g_gbuf[(size_t)NE * CAPACITY * INTER];
__device__ float g_ybuf[(size_t)NE * CAPACITY * HID];

// ---------------- helpers ----------------
// pack two fp32 -> f16x2 {lo, hi} with round-to-nearest (first asm src -> high half)
__device__ __forceinline__ uint32_t pack_f16x2(float lo, float hi) {
    uint32_t r;
    asm("cvt.rn.f16x2.f32 %0, %1, %2;" : "=r"(r) : "f"(hi), "f"(lo));
    return r;
}

// m16n8k16 fp16 MMA, fp32 accumulate
__device__ __forceinline__ void mma_f16(float* c, const uint32_t* a, uint32_t b0, uint32_t b1) {
    asm volatile(
        "mma.sync.aligned.m16n8k16.row.col.f32.f16.f16.f32 "
        "{%0,%1,%2,%3},{%4,%5,%6,%7},{%8,%9},{%0,%1,%2,%3};\n"
        : "+f"(c[0]), "+f"(c[1]), "+f"(c[2]), "+f"(c[3])
        : "r"(a[0]), "r"(a[1]), "r"(a[2]), "r"(a[3]), "r"(b0), "r"(b1));
}

// ---------------- kernel 0: zero expert counters ----------------
__global__ void zero_counts_kernel() {
    if (threadIdx.x < NE) g_counts[threadIdx.x] = 0;
}

// ---------------- kernel 1: router GEMM (fp32 FFMA, exact selection path) ----------
__global__ void __launch_bounds__(256) router_gemm_kernel(
    const float* __restrict__ hs, const float* __restrict__ rw) {
    __shared__ float As[32][65];
    __shared__ float Ws[32][81];
    const int m0 = blockIdx.x * 64;
    const int tid = threadIdx.x;
    const int tm = tid & 15;
    const int tn = tid >> 4;

    float acc[4][5];
#pragma unroll
    for (int i = 0; i < 4; i++)
#pragma unroll
        for (int j = 0; j < 5; j++) acc[i][j] = 0.f;

    for (int k0 = 0; k0 < HID; k0 += 32) {
#pragma unroll
        for (int i = 0; i < 8; i++) {
            int lin = tid + i * 256;
            int k = lin & 31, m = lin >> 5;
            As[k][m] = hs[(size_t)(m0 + m) * HID + k0 + k];
        }
#pragma unroll
        for (int i = 0; i < 10; i++) {
            int lin = tid + i * 256;
            int k = lin & 31, n = lin >> 5;
            Ws[k][n] = rw[(size_t)n * HID + k0 + k];
        }
        __syncthreads();
#pragma unroll
        for (int kk = 0; kk < 32; kk++) {
            float a[4], w[5];
#pragma unroll
            for (int i = 0; i < 4; i++) a[i] = As[kk][tm + 16 * i];
#pragma unroll
            for (int j = 0; j < 5; j++) w[j] = Ws[kk][tn + 16 * j];
#pragma unroll
            for (int i = 0; i < 4; i++)
#pragma unroll
                for (int j = 0; j < 5; j++) acc[i][j] = fmaf(a[i], w[j], acc[i][j]);
        }
        __syncthreads();
    }
#pragma unroll
    for (int i = 0; i < 4; i++)
#pragma unroll
        for (int j = 0; j < 5; j++)
            g_logits[(size_t)(m0 + tm + 16 * i) * NEZ + tn + 16 * j] = acc[i][j];
}

// ---------------- kernel 2: sigmoid + top-2 + capacity dispatch ----------------
__global__ void topk_dispatch_kernel(const float* __restrict__ bias) {
    int t = blockIdx.x * blockDim.x + threadIdx.x;
    if (t >= T_TOK) return;

    float sc[NEZ];
    for (int e = 0; e < NEZ; e++) {
        float l = g_logits[(size_t)t * NEZ + e];
        sc[e] = 1.f / (1.f + expf(-l));
    }
    int i1 = -1, i2 = -1;
    float b1 = -1e30f, b2 = -1e30f;
    for (int e = 0; e < NEZ; e++) {
        float b = sc[e] + bias[e];
        if (b > b1) { b2 = b1; i2 = i1; b1 = b; i1 = e; }
        else if (b > b2) { b2 = b; i2 = e; }
    }

    float zc = 0.f;
    int sel[2] = {i1, i2};
#pragma unroll
    for (int k = 0; k < 2; k++) {
        int e = sel[k];
        float w = sc[e];
        if (e >= NE) {
            zc += w;
            g_tok_p[t * 2 + k] = -1;
            g_tok_e[t * 2 + k] = 0;
            g_tok_w[t * 2 + k] = 0.f;
        } else {
            int p = atomicAdd(&g_counts[e], 1);
            if (p < CAPACITY) g_rows[e * CAPACITY + p] = t;
            g_tok_p[t * 2 + k] = p;
            g_tok_e[t * 2 + k] = e;
            g_tok_w[t * 2 + k] = w;
        }
    }
    g_zeroc[t] = zc;
}

// ---------------- kernel 3: fused gate/up fp16 GEMM + SiLU -> g_buf ----------------
// Tile 128M x 64N x 32K. 256 threads = 8 warps of 32x32 output each.
// A smem: half2 k-pairs, [128][20] u32 (16 data + 4 pad; LDS banks 20*grp+tg distinct).
// B smem: half2 k-pairs per column, [16][72] u32 (banks 72*tg+grp distinct).
__global__ void __launch_bounds__(256, 2) gemm_gateup_kernel(
    const float* __restrict__ hs,
    const float* __restrict__ wg,
    const float* __restrict__ wu) {
    const int e = blockIdx.z;
    const int Me = min(g_counts[e], CAPACITY);
    const int m0 = blockIdx.y * 128;
    if (m0 >= Me) return;
    const int n0 = blockIdx.x * 64;

    __shared__ uint32_t As32[2][128 * 20];
    __shared__ uint32_t Bg32[2][16 * 72];
    __shared__ uint32_t Bu32[2][16 * 72];
    __shared__ int toks[128];

    const int tid = threadIdx.x;
    const int lane = tid & 31, warp = tid >> 5;
    const int grp = lane >> 2, tg = lane & 3;
    const int wm = (warp >> 1) * 32, wn = (warp & 1) * 32;

    if (tid < 128) {
        int r = m0 + tid;
        toks[tid] = (r < Me) ? g_rows[e * CAPACITY + r] : -1;
    }
    __syncthreads();

    // A staging map: slot covers row (0..127) x float4-chunk fq (0..7) of 32 k
    const float* aP[4];
    int aDst[4];
#pragma unroll
    for (int i = 0; i < 4; i++) {
        int slot = tid + i * 256;
        int row = slot >> 3, fq = slot & 7;
        int tok = toks[row];
        aP[i] = (tok >= 0) ? hs + (size_t)tok * HID + fq * 4 : (const float*)0;
        aDst[i] = row * 20 + fq * 2;
    }
    // B staging map: j = k-pair row (0..15), n4 = 4 columns
    const int j = tid >> 4;
    const int n4 = (tid & 15) * 4;
    const float* gP = wg + (size_t)e * HID * INTER + (size_t)(2 * j) * INTER + n0 + n4;
    const float* uP = wu + (size_t)e * HID * INTER + (size_t)(2 * j) * INTER + n0 + n4;
    const int bDst = j * 72 + n4;

    float4 aR[4], gR0, gR1, uR0, uR1;
    auto fetch = [&](int k0) {
#pragma unroll
        for (int i = 0; i < 4; i++)
            aR[i] = aP[i] ? *(const float4*)(aP[i] + k0) : make_float4(0.f, 0.f, 0.f, 0.f);
        gR0 = *(const float4*)(gP + (size_t)k0 * INTER);
        gR1 = *(const float4*)(gP + (size_t)(k0 + 1) * INTER);
        uR0 = *(const float4*)(uP + (size_t)k0 * INTER);
        uR1 = *(const float4*)(uP + (size_t)(k0 + 1) * INTER);
    };
    auto stage = [&](int buf) {
#pragma unroll
        for (int i = 0; i < 4; i++) {
            uint2 v = make_uint2(pack_f16x2(aR[i].x, aR[i].y), pack_f16x2(aR[i].z, aR[i].w));
            *(uint2*)&As32[buf][aDst[i]] = v;
        }
        uint4 vg = make_uint4(pack_f16x2(gR0.x, gR1.x), pack_f16x2(gR0.y, gR1.y),
                              pack_f16x2(gR0.z, gR1.z), pack_f16x2(gR0.w, gR1.w));
        *(uint4*)&Bg32[buf][bDst] = vg;
        uint4 vu = make_uint4(pack_f16x2(uR0.x, uR1.x), pack_f16x2(uR0.y, uR1.y),
                              pack_f16x2(uR0.z, uR1.z), pack_f16x2(uR0.w, uR1.w));
        *(uint4*)&Bu32[buf][bDst] = vu;
    };

    float accG[2][4][4], accU[2][4][4];
#pragma unroll
    for (int a = 0; a < 2; a++)
#pragma unroll
        for (int b = 0; b < 4; b++)
#pragma unroll
            for (int c = 0; c < 4; c++) { accG[a][b][c] = 0.f; accU[a][b][c] = 0.f; }

    fetch(0);
    stage(0);
    __syncthreads();

    const int KT = HID / 32;   // 32
    for (int kt = 0; kt < KT; kt++) {
        const int p = kt & 1;
        if (kt + 1 < KT) fetch((kt + 1) * 32);
#pragma unroll
        for (int kb = 0; kb < 2; kb++) {       // two k16 sub-blocks
            const int p0 = kb * 8;             // k-pair base
            uint32_t af[2][4];
#pragma unroll
            for (int mi = 0; mi < 2; mi++) {
                int mr = wm + mi * 16;
                af[mi][0] = As32[p][(mr + grp    ) * 20 + p0 + tg    ];
                af[mi][1] = As32[p][(mr + grp + 8) * 20 + p0 + tg    ];
                af[mi][2] = As32[p][(mr + grp    ) * 20 + p0 + tg + 4];
                af[mi][3] = As32[p][(mr + grp + 8) * 20 + p0 + tg + 4];
            }
#pragma unroll
            for (int ni = 0; ni < 4; ni++) {
                int nc = wn + ni * 8 + grp;
                uint32_t bg0 = Bg32[p][(p0 + tg    ) * 72 + nc];
                uint32_t bg1 = Bg32[p][(p0 + tg + 4) * 72 + nc];
                uint32_t bu0 = Bu32[p][(p0 + tg    ) * 72 + nc];
                uint32_t bu1 = Bu32[p][(p0 + tg + 4) * 72 + nc];
#pragma unroll
                for (int mi = 0; mi < 2; mi++) {
                    mma_f16(accG[mi][ni], af[mi], bg0, bg1);
                    mma_f16(accU[mi][ni], af[mi], bu0, bu1);
                }
            }
        }
        if (kt + 1 < KT) stage(p ^ 1);
        __syncthreads();
    }

    // epilogue: g = silu(gate) * up
    float* gout = g_gbuf + (size_t)e * CAPACITY * INTER;
#pragma unroll
    for (int mi = 0; mi < 2; mi++) {
#pragma unroll
        for (int half = 0; half < 2; half++) {
            int mrow = m0 + wm + mi * 16 + grp + half * 8;
            if (mrow < Me) {
#pragma unroll
                for (int ni = 0; ni < 4; ni++) {
                    int n = n0 + wn + ni * 8 + tg * 2;
                    float gv0 = accG[mi][ni][half * 2 + 0];
                    float gv1 = accG[mi][ni][half * 2 + 1];
                    float uv0 = accU[mi][ni][half * 2 + 0];
                    float uv1 = accU[mi][ni][half * 2 + 1];
                    float o0 = (gv0 / (1.f + __expf(-gv0))) * uv0;
                    float o1 = (gv1 / (1.f + __expf(-gv1))) * uv1;
                    *(float2*)(gout + (size_t)mrow * INTER + n) = make_float2(o0, o1);
                }
            }
        }
    }
}

// ---------------- kernel 4: down-proj fp16 GEMM -> y_buf ----------------
// Tile 128M x 64N x 32K, same schedule.
__global__ void __launch_bounds__(256, 2) gemm_down_kernel(const float* __restrict__ wd) {
    const int e = blockIdx.z;
    const int Me = min(g_counts[e], CAPACITY);
    const int m0 = blockIdx.y * 128;
    if (m0 >= Me) return;
    const int n0 = blockIdx.x * 64;

    __shared__ uint32_t As32[2][128 * 20];
    __shared__ uint32_t Bs32[2][16 * 72];

    const int tid = threadIdx.x;
    const int lane = tid & 31, warp = tid >> 5;
    const int grp = lane >> 2, tg = lane & 3;
    const int wm = (warp >> 1) * 32, wn = (warp & 1) * 32;

    const float* gA = g_gbuf + ((size_t)e * CAPACITY + m0) * INTER;
    const float* aP[4];
    int aDst[4];
#pragma unroll
    for (int i = 0; i < 4; i++) {
        int slot = tid + i * 256;
        int row = slot >> 3, fq = slot & 7;
        aP[i] = (m0 + row < CAPACITY) ? gA + (size_t)row * INTER + fq * 4 : (const float*)0;
        aDst[i] = row * 20 + fq * 2;
    }
    const int j = tid >> 4;
    const int n4 = (tid & 15) * 4;
    const float* bP = wd + (size_t)e * INTER * HID + (size_t)(2 * j) * HID + n0 + n4;
    const int bDst = j * 72 + n4;

    float4 aR[4], bR0, bR1;
    auto fetch = [&](int k0) {
#pragma unroll
        for (int i = 0; i < 4; i++)
            aR[i] = aP[i] ? *(const float4*)(aP[i] + k0) : make_float4(0.f, 0.f, 0.f, 0.f);
        bR0 = *(const float4*)(bP + (size_t)k0 * HID);
        bR1 = *(const float4*)(bP + (size_t)(k0 + 1) * HID);
    };
    auto stage = [&](int buf) {
#pragma unroll
        for (int i = 0; i < 4; i++) {
            uint2 v = make_uint2(pack_f16x2(aR[i].x, aR[i].y), pack_f16x2(aR[i].z, aR[i].w));
            *(uint2*)&As32[buf][aDst[i]] = v;
        }
        uint4 vb = make_uint4(pack_f16x2(bR0.x, bR1.x), pack_f16x2(bR0.y, bR1.y),
                              pack_f16x2(bR0.z, bR1.z), pack_f16x2(bR0.w, bR1.w));
        *(uint4*)&Bs32[buf][bDst] = vb;
    };

    float acc[2][4][4];
#pragma unroll
    for (int a = 0; a < 2; a++)
#pragma unroll
        for (int b = 0; b < 4; b++)
#pragma unroll
            for (int c = 0; c < 4; c++) acc[a][b][c] = 0.f;

    fetch(0);
    stage(0);
    __syncthreads();

    const int KT = INTER / 32;   // 16
    for (int kt = 0; kt < KT; kt++) {
        const int p = kt & 1;
        if (kt + 1 < KT) fetch((kt + 1) * 32);
#pragma unroll
        for (int kb = 0; kb < 2; kb++) {
            const int p0 = kb * 8;
            uint32_t af[2][4];
#pragma unroll
            for (int mi = 0; mi < 2; mi++) {
                int mr = wm + mi * 16;
                af[mi][0] = As32[p][(mr + grp    ) * 20 + p0 + tg    ];
                af[mi][1] = As32[p][(mr + grp + 8) * 20 + p0 + tg    ];
                af[mi][2] = As32[p][(mr + grp    ) * 20 + p0 + tg + 4];
                af[mi][3] = As32[p][(mr + grp + 8) * 20 + p0 + tg + 4];
            }
#pragma unroll
            for (int ni = 0; ni < 4; ni++) {
                int nc = wn + ni * 8 + grp;
                uint32_t b0 = Bs32[p][(p0 + tg    ) * 72 + nc];
                uint32_t b1 = Bs32[p][(p0 + tg + 4) * 72 + nc];
#pragma unroll
                for (int mi = 0; mi < 2; mi++) mma_f16(acc[mi][ni], af[mi], b0, b1);
            }
        }
        if (kt + 1 < KT) stage(p ^ 1);
        __syncthreads();
    }

    float* yout = g_ybuf + (size_t)e * CAPACITY * HID;
#pragma unroll
    for (int mi = 0; mi < 2; mi++) {
#pragma unroll
        for (int half = 0; half < 2; half++) {
            int mrow = m0 + wm + mi * 16 + grp + half * 8;
            if (mrow < Me) {
#pragma unroll
                for (int ni = 0; ni < 4; ni++) {
                    int n = n0 + wn + ni * 8 + tg * 2;
                    *(float2*)(yout + (size_t)mrow * HID + n) =
                        make_float2(acc[mi][ni][half * 2 + 0], acc[mi][ni][half * 2 + 1]);
                }
            }
        }
    }
}

// ---------------- kernel 5: deterministic combine ----------------
__global__ void combine_kernel(const float* __restrict__ hs, float* __restrict__ out) {
    const int t = blockIdx.x;
    const int j = threadIdx.x;
    float4 hv = *(const float4*)(hs + (size_t)t * HID + j * 4);
    float zc = g_zeroc[t];
    float4 r;
    r.x = zc * hv.x; r.y = zc * hv.y; r.z = zc * hv.z; r.w = zc * hv.w;
#pragma unroll
    for (int k = 0; k < 2; k++) {
        int p = g_tok_p[t * 2 + k];
        if (p >= 0 && p < CAPACITY) {
            int e = g_tok_e[t * 2 + k];
            float w = g_tok_w[t * 2 + k];
            float4 y = *(const float4*)(g_ybuf + ((size_t)e * CAPACITY + p) * HID + j * 4);
            r.x = fmaf(w, y.x, r.x);
            r.y = fmaf(w, y.y, r.y);
            r.z = fmaf(w, y.z, r.z);
            r.w = fmaf(w, y.w, r.w);
        }
    }
    r.x *= SCALE_F; r.y *= SCALE_F; r.z *= SCALE_F; r.w *= SCALE_F;
    *(float4*)(out + (size_t)t * HID + j * 4) = r;
}

// ---------------- launcher ----------------
extern "C" void kernel_launch(void* const* d_in, const int* in_sizes, int n_in,
                              void* d_out, int out_size) {
    const float* hs   = (const float*)d_in[0];   // [4096,1024]
    const float* rw   = (const float*)d_in[1];   // [80,1024]
    const float* bias = (const float*)d_in[2];   // [80]
    const float* wg   = (const float*)d_in[3];   // [64,1024,512]
    const float* wu   = (const float*)d_in[4];   // [64,1024,512]
    const float* wd   = (const float*)d_in[5];   // [64,512,1024]
    float* out = (float*)d_out;                  // [4096,1024]

    zero_counts_kernel<<<1, 64>>>();
    router_gemm_kernel<<<T_TOK / 64, 256>>>(hs, rw);
    topk_dispatch_kernel<<<T_TOK / 128, 128>>>(bias);
    gemm_gateup_kernel<<<dim3(INTER / 64, (CAPACITY + 127) / 128, NE), 256>>>(hs, wg, wu);
    gemm_down_kernel<<<dim3(HID / 64, (CAPACITY + 127) / 128, NE), 256>>>(wd);
    combine_kernel<<<T_TOK, 256>>>(hs, out);
}